// round 14
// baseline (speedup 1.0000x reference)
#include <cuda_runtime.h>
#include <math.h>

#define IN_F   1024
#define OUT_F  512
#define BATCH  256
#define CAP    96
#define TLO    0.04f
#define THI    0.96f

// Transposed no_edge bit matrix: [i][o_word], bit = o&31. 64 KB.
__device__ unsigned g_maskT[IN_F * (OUT_F / 32)];
// Sorted candidate lists per (side, batch): value, index, raw count.
__device__ float g_sv [2][BATCH][CAP];
__device__ int   g_sci[2][BATCH][CAP];
__device__ int   g_cnt[2][BATCH];

// ---------------------------------------------------------------------------
// no_edge = argmax(etc + gumbel(u)) == 1, i.e. (etc1+g1) > (etc0+g0) strictly
// (argmax tie -> index 0). g(u) = -log(-log(u+eps)+eps) is strictly
// increasing, so for etc0==etc1 this is exactly u1>u0; full gumbel math as
// the general fallback.
// ---------------------------------------------------------------------------
__device__ __forceinline__ bool no_edge_of(float e0, float e1, float u0, float u1) {
    if (e0 == e1) return u1 > u0;
    const float eps = 1e-10f;
    float g0 = -logf(-logf(u0 + eps) + eps);
    float g1 = -logf(-logf(u1 + eps) + eps);
    return (e1 + g1) > (e0 + g0);
}

// ---------------------------------------------------------------------------
// Phase 1, 512 blocks x 256 threads, two independent roles (no inter-role
// dependency -> no sync; stream order gates the resolve kernel):
//   blocks 0..255  : mask tile build + ballot transpose (proven R9 code)
//   blocks 256..511: candidate extraction + rank-sort for batch bid-256,
//                    sorted lists spilled to global scratch
// ---------------------------------------------------------------------------
__global__ __launch_bounds__(256)
void phase1_kernel(const float* __restrict__ etc, const float* __restrict__ un,
                   const float* __restrict__ x) {
    __shared__ unsigned bits[64][33];          // mask role
    __shared__ float    cv[2][CAP];            // extract role
    __shared__ int      ci[2][CAP];
    __shared__ int      n_s[2];

    const int t    = threadIdx.x;
    const int lane = t & 31;
    const int w    = t >> 5;

    if (blockIdx.x < 256) {
        // ---------------- mask tile role ----------------
        const int bid = blockIdx.x;
        const int ow  = bid & 15;              // o-word index (OUT_F/32)
        const int it  = bid >> 4;              // 64-wide i-tile index

        const int o_local = t >> 3;
        const int i_local = (t & 7) << 2;
        const size_t gp0 = (size_t)(ow * 32 + o_local) * IN_F + (it * 64 + i_local);
        const size_t f0  = gp0 >> 1;
        const size_t f1  = f0 + 16;

        float4 ea0 = ((const float4*)etc)[f0];
        float4 eb0 = ((const float4*)etc)[f0 + 1];
        float4 ea1 = ((const float4*)etc)[f1];
        float4 eb1 = ((const float4*)etc)[f1 + 1];
        float4 ua0 = ((const float4*)un)[f0];
        float4 ub0 = ((const float4*)un)[f0 + 1];
        float4 ua1 = ((const float4*)un)[f1];
        float4 ub1 = ((const float4*)un)[f1 + 1];

        bits[i_local + 0][o_local]      = no_edge_of(ea0.x, ea0.y, ua0.x, ua0.y) ? 1u : 0u;
        bits[i_local + 1][o_local]      = no_edge_of(ea0.z, ea0.w, ua0.z, ua0.w) ? 1u : 0u;
        bits[i_local + 2][o_local]      = no_edge_of(eb0.x, eb0.y, ub0.x, ub0.y) ? 1u : 0u;
        bits[i_local + 3][o_local]      = no_edge_of(eb0.z, eb0.w, ub0.z, ub0.w) ? 1u : 0u;
        bits[i_local + 32 + 0][o_local] = no_edge_of(ea1.x, ea1.y, ua1.x, ua1.y) ? 1u : 0u;
        bits[i_local + 32 + 1][o_local] = no_edge_of(ea1.z, ea1.w, ua1.z, ua1.w) ? 1u : 0u;
        bits[i_local + 32 + 2][o_local] = no_edge_of(eb1.x, eb1.y, ub1.x, ub1.y) ? 1u : 0u;
        bits[i_local + 32 + 3][o_local] = no_edge_of(eb1.z, eb1.w, ub1.z, ub1.w) ? 1u : 0u;

        __syncthreads();

        #pragma unroll
        for (int r = 0; r < 8; r++) {
            const int i = (w << 3) + r;
            unsigned word = __ballot_sync(0xFFFFFFFFu, bits[i][lane] != 0u);
            if (lane == 0) g_maskT[(size_t)(it * 64 + i) * 16 + ow] = word;
        }
    } else {
        // ---------------- extraction + sort role ----------------
        const int b = blockIdx.x - 256;
        if (t == 0) { n_s[0] = 0; n_s[1] = 0; }
        __syncthreads();

        float4 v4 = ((const float4*)(x + (size_t)b * IN_F))[t];
        float vals[4] = {v4.x, v4.y, v4.z, v4.w};
        #pragma unroll
        for (int j = 0; j < 4; j++) {
            float v = vals[j];
            int   i = 4 * t + j;

            unsigned mlo = __ballot_sync(0xFFFFFFFFu, v < TLO);
            if (v < TLO) {
                int rank = __popc(mlo & ((1u << lane) - 1u));
                int base = 0, lead = __ffs(mlo) - 1;
                if (lane == lead) base = atomicAdd(&n_s[0], __popc(mlo));
                base = __shfl_sync(mlo, base, lead);
                int p = base + rank;
                if (p < CAP) { cv[0][p] = v; ci[0][p] = i; }
            }
            unsigned mhi = __ballot_sync(0xFFFFFFFFu, v > THI);
            if (v > THI) {
                int rank = __popc(mhi & ((1u << lane) - 1u));
                int base = 0, lead = __ffs(mhi) - 1;
                if (lane == lead) base = atomicAdd(&n_s[1], __popc(mhi));
                base = __shfl_sync(mhi, base, lead);
                int p = base + rank;
                if (p < CAP) { cv[1][p] = v; ci[1][p] = i; }
            }
        }
        __syncthreads();

        const int n0 = min(n_s[0], CAP);
        const int n1 = min(n_s[1], CAP);

        // Rank-sort: threads 0..127 handle list0 (ascending),
        //            threads 128..255 handle list1 (descending). CAP<=128.
        const int side = t >> 7;
        const int tl   = t & 127;
        const int n    = side ? n1 : n0;
        if (tl < n) {
            float vme = cv[side][tl];
            int r = 0;
            if (side == 0) {
                for (int j = 0; j < n; j++) {
                    float vj = cv[0][j];
                    r += (vj < vme) || (vj == vme && j < tl);
                }
            } else {
                for (int j = 0; j < n; j++) {
                    float vj = cv[1][j];
                    r += (vj > vme) || (vj == vme && j < tl);
                }
            }
            g_sv [side][b][r] = vme;
            g_sci[side][b][r] = ci[side][tl];
        }
        if (t == 0) { g_cnt[0][b] = n_s[0]; g_cnt[1][b] = n_s[1]; }
    }
}

// ---------------------------------------------------------------------------
// Resolve: one block per batch, 512 threads. t<256: min outputs o=2t;
// t>=256: max outputs o=2(t-256)+1. Load sorted lists, stage their mask rows,
// take the FIRST unmasked candidate = exact extremum. Deterministic unrolled
// full-scan fallback reading x from global (prob ~1e-9/output, or overflow).
// Clamp to identity offsets (2 / -1) handles all-no-edge rows exactly.
// ---------------------------------------------------------------------------
__global__ __launch_bounds__(512)
void resolve_kernel(const float* __restrict__ x, float* __restrict__ out) {
    __shared__ float    sv[2][CAP];
    __shared__ int      sci[2][CAP];
    __shared__ unsigned cm[2][CAP][16];
    __shared__ float    so_out[OUT_F];
    __shared__ int      ncl[2];

    const int t = threadIdx.x;
    const int b = blockIdx.x;

    if (t < 2) ncl[t] = g_cnt[t][b];
    // Load both sorted lists unconditionally (CAP*2 values + CAP*2 indices =
    // 384 words over 512 threads, coalesced).
    if (t < CAP)                      sv[0][t]        = g_sv [0][b][t];
    else if (t < 2 * CAP)             sv[1][t - CAP]  = g_sv [1][b][t - CAP];
    else if (t < 3 * CAP)             sci[0][t - 2*CAP] = g_sci[0][b][t - 2*CAP];
    else if (t < 4 * CAP)             sci[1][t - 3*CAP] = g_sci[1][b][t - 3*CAP];
    __syncthreads();

    const int n0   = min(ncl[0], CAP);
    const int n1   = min(ncl[1], CAP);

    // Stage candidate mask rows in sorted order (both lists, cooperative).
    for (int k = t; k < n0 * 16; k += 512) {
        int c = k >> 4;
        cm[0][c][k & 15] = __ldg(&g_maskT[(size_t)sci[0][c] * 16 + (k & 15)]);
    }
    for (int k = t; k < n1 * 16; k += 512) {
        int c = k >> 4;
        cm[1][c][k & 15] = __ldg(&g_maskT[(size_t)sci[1][c] * 16 + (k & 15)]);
    }
    __syncthreads();

    const int side = t >> 8;        // 0 = min, 1 = max
    const int tl   = t & 255;
    const int n    = side ? n1 : n0;
    const bool ovf = (ncl[side] > CAP);

    const int o  = 2 * tl + side;
    const int wo = o >> 5, bo = o & 31;
    const float INF  = __int_as_float(0x7F800000);
    const float NINF = __int_as_float(0xFF800000);
    const float init = side ? NINF : INF;

    float acc = init;
    if (!ovf) {
        for (int c = 0; c < n; c++) {
            unsigned wd = cm[side][c][wo];
            if (!((wd >> bo) & 1u)) { acc = sv[side][c]; break; }
        }
    }
    if (acc == init) {   // no unmasked candidate (or overflow): full scan, MLP 8
        const unsigned* __restrict__ mt = g_maskT;
        const float*    xr = x + (size_t)b * IN_F;
        if (side) {
            for (int i = 0; i < IN_F; i += 8) {
                #pragma unroll
                for (int u = 0; u < 8; u++) {
                    unsigned wd = __ldg(&mt[(size_t)(i + u) * 16 + wo]);
                    if (!((wd >> bo) & 1u)) acc = fmaxf(acc, __ldg(&xr[i + u]));
                }
            }
        } else {
            for (int i = 0; i < IN_F; i += 8) {
                #pragma unroll
                for (int u = 0; u < 8; u++) {
                    unsigned wd = __ldg(&mt[(size_t)(i + u) * 16 + wo]);
                    if (!((wd >> bo) & 1u)) acc = fminf(acc, __ldg(&xr[i + u]));
                }
            }
        }
    }

    so_out[o] = side ? fmaxf(acc, -1.0f) : fminf(acc, 2.0f);
    __syncthreads();

    if (t < OUT_F / 4) {
        ((float4*)(out + (size_t)b * OUT_F))[t] = ((const float4*)so_out)[t];
    }
}

extern "C" void kernel_launch(void* const* d_in, const int* in_sizes, int n_in,
                              void* d_out, int out_size) {
    const float* x   = (const float*)d_in[0];  // [256, 1024]
    const float* etc = (const float*)d_in[1];  // [512, 1024, 2]
    const float* un  = (const float*)d_in[2];  // [512, 1024, 2]
    float* out = (float*)d_out;                // [256, 512]

    phase1_kernel<<<512, 256>>>(etc, un, x);   // mask tiles + extraction, overlapped
    resolve_kernel<<<BATCH, 512>>>(x, out);    // lean resolve
}